// round 15
// baseline (speedup 1.0000x reference)
#include <cuda_runtime.h>
#include <cuda_fp16.h>
#include <cstdint>

// BiAttention (BiDAF): N=64, T=1024, J=64, D2=200.
// Main: fp16 mma.sync + ldmatrix fragment loads, persistent CTAs.
#define NEGV (-10000000.0f)
__device__ float g_Smax[64 * 1024];

#define WB_B  12800
#define WB_UT 19200
#define OFF_W   105600
#define OFF_HWH 108000
#define OFF_UWU 108512
#define OFF_QM  108768
#define SMEM_BYTES 109056
#define GRID_MAIN 296
#define NTILES 512

__device__ __forceinline__ void mma16816(float* c, uint32_t a0, uint32_t a1, uint32_t a2, uint32_t a3,
                                         uint32_t b0, uint32_t b1) {
    asm volatile("mma.sync.aligned.m16n8k16.row.col.f32.f16.f16.f32 "
                 "{%0,%1,%2,%3},{%4,%5,%6,%7},{%8,%9},{%0,%1,%2,%3};"
                 : "+f"(c[0]), "+f"(c[1]), "+f"(c[2]), "+f"(c[3])
                 : "r"(a0), "r"(a1), "r"(a2), "r"(a3), "r"(b0), "r"(b1));
}
__device__ __forceinline__ void mma1688(float* c, uint32_t a0, uint32_t a1, uint32_t b0) {
    asm volatile("mma.sync.aligned.m16n8k8.row.col.f32.f16.f16.f32 "
                 "{%0,%1,%2,%3},{%4,%5},{%6},{%0,%1,%2,%3};"
                 : "+f"(c[0]), "+f"(c[1]), "+f"(c[2]), "+f"(c[3])
                 : "r"(a0), "r"(a1), "r"(b0));
}
__device__ __forceinline__ void ldsm4(uint32_t* r, unsigned a) {
    asm volatile("ldmatrix.sync.aligned.m8n8.x4.shared.b16 {%0,%1,%2,%3}, [%4];"
                 : "=r"(r[0]), "=r"(r[1]), "=r"(r[2]), "=r"(r[3]) : "r"(a));
}
__device__ __forceinline__ void ldsm2(uint32_t* r, unsigned a) {
    asm volatile("ldmatrix.sync.aligned.m8n8.x2.shared.b16 {%0,%1}, [%2];"
                 : "=r"(r[0]), "=r"(r[1]) : "r"(a));
}
__device__ __forceinline__ uint32_t pack2h(float a, float b) {
    __half2 h = __floats2half2_rn(a, b);
    return *(uint32_t*)&h;
}
__device__ __forceinline__ unsigned smem_u32(const void* p) {
    unsigned a;
    asm("{ .reg .u64 t; cvta.to.shared.u64 t, %1; cvt.u32.u64 %0, t; }" : "=r"(a) : "l"(p));
    return a;
}

__global__ void __launch_bounds__(256, 2)
bi_attn_main(const float* __restrict__ H, const float* __restrict__ U,
             const float* __restrict__ q_mask, const float* __restrict__ wv,
             const float* __restrict__ bptr, float* __restrict__ G)
{
    extern __shared__ char smc[];
    uint32_t* sm32 = (uint32_t*)smc;
    const unsigned sb = smem_u32(smc);
    float* sW   = (float*)(smc + OFF_W);
    float* sHwh = (float*)(smc + OFF_HWH);
    float* sUwu = (float*)(smc + OFF_UWU);
    float* sQm  = (float*)(smc + OFF_QM);

    const int tid = threadIdx.x, wid = tid >> 5, lane = tid & 31;
    const float bval = bptr[0];

    for (int i = tid; i < 600; i += 256) sW[i] = wv[i];

    const int ar = tid >> 1, ah = tid & 1;
    const int bj = tid >> 2, bq = tid & 3;
    const int r = lane >> 2, cq = lane & 3;

    // ldmatrix per-lane addresses
    const int li = lane & 7, g = lane >> 3;
    // A/P rows: tiles (r0-7,k0-7),(r8-15,k0-7),(r0-7,k8-15),(r8-15,k8-15)
    const unsigned aLd = sb + (unsigned)(((wid * 16 + li + (g & 1) * 8) * 100 + (g >> 1) * 4) * 4);
    // B (U rows): tiles (nt0 rows,k0-7),(nt0,k8-15),(nt1 rows,k0-7),(nt1,k8-15)
    const unsigned bLd = sb + (unsigned)(((WB_B + (li + (g >> 1) * 8) * 100) + (g & 1) * 4) * 4);
    // Ut rows: same tile pattern, stride 36 words
    const unsigned uLd = sb + (unsigned)(((WB_UT + (li + (g >> 1) * 8) * 36) + (g & 1) * 4) * 4);

    #pragma unroll 1
    for (int tile = blockIdx.x; tile < NTILES; tile += GRID_MAIN) {
        const int n  = tile >> 3;
        const int m0 = (tile & 7) * 128;

        __syncthreads();   // previous tile fully done with smem
        if (tid < 64) sQm[tid] = q_mask[n * 64 + tid];

        // ============ stage everything ============
        float hwh_acc = 0.f, uwu_acc = 0.f;
        {
            const float* hrow = H + (size_t)(n * 1024 + m0 + ar) * 200 + ah * 100;
            const float* wh0  = sW + ah * 100;
            const float* wu0  = sW + 400 + ah * 100;
            uint32_t* dst = sm32 + ar * 100 + ah * 50;
            #pragma unroll
            for (int c = 0; c < 25; c++) {
                const float4 h4 = *(const float4*)(hrow + c * 4);
                const float4 wh = *(const float4*)(wh0 + c * 4);
                const float4 wu = *(const float4*)(wu0 + c * 4);
                hwh_acc += h4.x * wh.x + h4.y * wh.y + h4.z * wh.z + h4.w * wh.w;
                uint2 st;
                st.x = pack2h(h4.x * wu.x, h4.y * wu.y);
                st.y = pack2h(h4.z * wu.z, h4.w * wu.w);
                *(uint2*)(dst + c * 2) = st;
            }
        }
        {
            const float* urow = U + (size_t)(n * 64 + bj) * 200;
            uint32_t* dst = sm32 + WB_B + bj * 100;
            #pragma unroll
            for (int c = bq; c < 50; c += 4) {
                const float4 u4 = *(const float4*)(urow + c * 4);
                const float4 wu = *(const float4*)(sW + 200 + c * 4);
                uwu_acc += u4.x * wu.x + u4.y * wu.y + u4.z * wu.z + u4.w * wu.w;
                uint2 st;
                st.x = pack2h(u4.x, u4.y);
                st.y = pack2h(u4.z, u4.w);
                *(uint2*)(dst + c * 2) = st;
            }
        }
        if (tid < 200) {   // Ut[d][j] = U[j][d]
            const float* up = U + (size_t)n * 12800 + tid;
            uint32_t* dst = sm32 + WB_UT + tid * 36;
            #pragma unroll 8
            for (int j = 0; j < 64; j += 2)
                dst[j >> 1] = pack2h(up[(size_t)j * 200], up[(size_t)(j + 1) * 200]);
        }
        {
            float hv = hwh_acc + __shfl_xor_sync(0xffffffffu, hwh_acc, 1);
            if (ah == 0) sHwh[ar] = hv;
            float uv = uwu_acc;
            uv += __shfl_xor_sync(0xffffffffu, uv, 1);
            uv += __shfl_xor_sync(0xffffffffu, uv, 2);
            if (bq == 0) sUwu[bj] = uv;
        }
        __syncthreads();   // operands + row-dots visible

        // ============ GEMM1 (K=200 = 12x16 + 8) via ldmatrix ============
        float acc1[8][4];
        #pragma unroll
        for (int t = 0; t < 8; t++)
            #pragma unroll
            for (int u = 0; u < 4; u++) acc1[t][u] = 0.f;

        #pragma unroll 4
        for (int kst = 0; kst < 12; kst++) {
            uint32_t A[4];
            ldsm4(A, aLd + kst * 32);
            #pragma unroll
            for (int p = 0; p < 4; p++) {
                uint32_t Bv[4];
                ldsm4(Bv, bLd + p * 6400 + kst * 32);
                mma16816(acc1[2 * p],     A[0], A[1], A[2], A[3], Bv[0], Bv[1]);
                mma16816(acc1[2 * p + 1], A[0], A[1], A[2], A[3], Bv[2], Bv[3]);
            }
        }
        {   // k = 192..199 tail: x4 reads, use only k0-7 tiles (r0/r2); extra regs junk-but-in-range
            uint32_t A[4];
            ldsm4(A, aLd + 12 * 32);
            #pragma unroll
            for (int p = 0; p < 4; p++) {
                uint32_t Bv[4];
                ldsm4(Bv, bLd + p * 6400 + 12 * 32);
                mma1688(acc1[2 * p],     A[0], A[1], Bv[0]);
                mma1688(acc1[2 * p + 1], A[0], A[1], Bv[2]);
            }
        }

        // ============ softmax over j ============
        const int row0 = wid * 16 + r, row1 = row0 + 8;
        const float hwh0 = sHwh[row0], hwh1 = sHwh[row1];
        float mx0 = -3.4e38f, mx1 = -3.4e38f, smx0 = -3.4e38f, smx1 = -3.4e38f;
        #pragma unroll
        for (int nt = 0; nt < 8; nt++) {
            #pragma unroll
            for (int i = 0; i < 2; i++) {
                const int nn = nt * 8 + cq * 2 + i;
                const float q = sQm[nn], uw = sUwu[nn];
                const float s0 = acc1[nt][i] + hwh0 + uw + bval;
                const float s1 = acc1[nt][2 + i] + hwh1 + uw + bval;
                acc1[nt][i] = s0 * q; acc1[nt][2 + i] = s1 * q;
                mx0 = fmaxf(mx0, s0 * q); mx1 = fmaxf(mx1, s1 * q);
                smx0 = fmaxf(smx0, (q != 0.f) ? s0 : NEGV);
                smx1 = fmaxf(smx1, (q != 0.f) ? s1 : NEGV);
            }
        }
        #pragma unroll
        for (int o = 1; o <= 2; o <<= 1) {
            mx0 = fmaxf(mx0, __shfl_xor_sync(0xffffffffu, mx0, o));
            mx1 = fmaxf(mx1, __shfl_xor_sync(0xffffffffu, mx1, o));
            smx0 = fmaxf(smx0, __shfl_xor_sync(0xffffffffu, smx0, o));
            smx1 = fmaxf(smx1, __shfl_xor_sync(0xffffffffu, smx1, o));
        }
        float E0 = 0.f, M0 = 0.f, E1 = 0.f, M1 = 0.f;
        #pragma unroll
        for (int nt = 0; nt < 8; nt++) {
            #pragma unroll
            for (int i = 0; i < 2; i++) {
                const int nn = nt * 8 + cq * 2 + i;
                const float q = sQm[nn];
                const float e0 = __expf(acc1[nt][i] - mx0);
                const float e1 = __expf(acc1[nt][2 + i] - mx1);
                E0 += e0; E1 += e1;
                const float q0 = e0 * q, q1 = e1 * q;
                M0 += q0; M1 += q1;
                acc1[nt][i] = q0; acc1[nt][2 + i] = q1;
            }
        }
        #pragma unroll
        for (int o = 1; o <= 2; o <<= 1) {
            E0 += __shfl_xor_sync(0xffffffffu, E0, o);
            M0 += __shfl_xor_sync(0xffffffffu, M0, o);
            E1 += __shfl_xor_sync(0xffffffffu, E1, o);
            M1 += __shfl_xor_sync(0xffffffffu, M1, o);
        }
        const float inv0 = 1.0f / (M0 + 1e-13f * E0);
        const float inv1 = 1.0f / (M1 + 1e-13f * E1);
        if (cq == 0) {
            g_Smax[(n << 10) + m0 + row0] = smx0;
            g_Smax[(n << 10) + m0 + row1] = smx1;
        }

        // P (fp16) into this warp's OWN A rows — warp-private
        #pragma unroll
        for (int nt = 0; nt < 8; nt++) {
            sm32[row0 * 100 + nt * 4 + cq] = pack2h(acc1[nt][0] * inv0, acc1[nt][1] * inv0);
            sm32[row1 * 100 + nt * 4 + cq] = pack2h(acc1[nt][2] * inv1, acc1[nt][3] * inv1);
        }
        __syncwarp();

        // ============ GEMM2 + fused epilogue ============
        const size_t grow0 = (size_t)(n * 1024 + m0 + row0) * 800;
        const size_t grow1 = (size_t)(n * 1024 + m0 + row1) * 800;
        const float* hg0 = H + (size_t)(n * 1024 + m0 + row0) * 200;
        const float* hg1 = H + (size_t)(n * 1024 + m0 + row1) * 200;

        #pragma unroll 1
        for (int pass = 0; pass < 5; pass++) {
            const int dbase = pass * 40;
            float acc2[5][4];
            #pragma unroll
            for (int t = 0; t < 5; t++)
                #pragma unroll
                for (int u = 0; u < 4; u++) acc2[t][u] = 0.f;

            #pragma unroll
            for (int kst = 0; kst < 4; kst++) {
                uint32_t A[4];
                ldsm4(A, aLd + kst * 32);      // P lives in words 0..31 of A rows
                #pragma unroll
                for (int q = 0; q < 2; q++) {
                    uint32_t Bv[4];
                    ldsm4(Bv, uLd + (unsigned)((dbase + q * 16) * 144) + kst * 32);
                    mma16816(acc2[2 * q],     A[0], A[1], A[2], A[3], Bv[0], Bv[1]);
                    mma16816(acc2[2 * q + 1], A[0], A[1], A[2], A[3], Bv[2], Bv[3]);
                }
                uint32_t C2[2];
                ldsm2(C2, uLd + (unsigned)((dbase + 32) * 144) + kst * 32);
                mma16816(acc2[4], A[0], A[1], A[2], A[3], C2[0], C2[1]);
            }
            #pragma unroll
            for (int nt = 0; nt < 5; nt++) {
                const int d = dbase + nt * 8 + cq * 2;
                const float2 h0 = *(const float2*)(hg0 + d);
                const float2 h1 = *(const float2*)(hg1 + d);
                float2 u0 = {acc2[nt][0], acc2[nt][1]};
                float2 u1 = {acc2[nt][2], acc2[nt][3]};
                float2 m0v = {h0.x * u0.x, h0.y * u0.y};
                float2 m1v = {h1.x * u1.x, h1.y * u1.y};
                *(float2*)(G + grow0 + d)       = h0;
                *(float2*)(G + grow0 + 200 + d) = u0;
                *(float2*)(G + grow0 + 400 + d) = m0v;
                *(float2*)(G + grow1 + d)       = h1;
                *(float2*)(G + grow1 + 200 + d) = u1;
                *(float2*)(G + grow1 + 400 + d) = m1v;
            }
        }
    }
}

// ---- fused tail (unchanged, passing): cluster of 8 CTAs per n ----
__device__ __forceinline__ void st_cl(unsigned la, int rk, float v) {
    asm volatile("{ .reg .b32 ra; mapa.shared::cluster.u32 ra, %0, %1; st.shared::cluster.f32 [ra], %2; }"
                 :: "r"(la), "r"(rk), "f"(v) : "memory");
}
__device__ __forceinline__ float ld_cl(unsigned la, int rk) {
    float v;
    asm volatile("{ .reg .b32 ra; mapa.shared::cluster.u32 ra, %1, %2; ld.shared::cluster.f32 %0, [ra]; }"
                 : "=f"(v) : "r"(la), "r"(rk) : "memory");
    return v;
}
#define CSYNC() do { asm volatile("barrier.cluster.arrive.aligned;" ::: "memory"); \
                     asm volatile("barrier.cluster.wait.aligned;" ::: "memory"); } while (0)

__global__ void __launch_bounds__(256, 1) __cluster_dims__(8, 1, 1)
tail_fused(const float* __restrict__ H, const float* __restrict__ c_mask,
           float* __restrict__ G)
{
    __shared__ float sa[128];
    __shared__ float s_mx[8], s_E[8], s_M[8];
    __shared__ float red[8], redE[8], redM[8];
    __shared__ float part[8][208];
    __shared__ float ppart[200];
    __shared__ float hbar[200];

    const int bx = blockIdx.x, n = bx >> 3, s = bx & 7;
    const int tid = threadIdx.x, wid = tid >> 5, lane = tid & 31;

    float v = -3.4e38f, c = 0.f;
    if (tid < 128) {
        c = c_mask[n * 1024 + s * 128 + tid];
        v = g_Smax[n * 1024 + s * 128 + tid] * c;
    }
    float mx = v;
    #pragma unroll
    for (int o = 16; o > 0; o >>= 1) mx = fmaxf(mx, __shfl_xor_sync(0xffffffffu, mx, o));
    if (lane == 0) red[wid] = mx;
    __syncthreads();
    mx = red[0];
    #pragma unroll
    for (int i = 1; i < 8; i++) mx = fmaxf(mx, red[i]);
    if (tid == 0) {
        const unsigned a = smem_u32(&s_mx[s]);
        #pragma unroll
        for (int r = 0; r < 8; r++) st_cl(a, r, mx);
    }
    CSYNC();
    float gmx = s_mx[0];
    #pragma unroll
    for (int i = 1; i < 8; i++) gmx = fmaxf(gmx, s_mx[i]);

    float e = 0.f;
    if (tid < 128) { e = __expf(v - gmx); sa[tid] = e * c; }
    float El = e, Ml = e * c;
    #pragma unroll
    for (int o = 16; o > 0; o >>= 1) {
        El += __shfl_xor_sync(0xffffffffu, El, o);
        Ml += __shfl_xor_sync(0xffffffffu, Ml, o);
    }
    if (lane == 0) { redE[wid] = El; redM[wid] = Ml; }
    __syncthreads();
    El = 0.f; Ml = 0.f;
    #pragma unroll
    for (int i = 0; i < 8; i++) { El += redE[i]; Ml += redM[i]; }
    if (tid == 0) {
        const unsigned aE = smem_u32(&s_E[s]);
        const unsigned aM = smem_u32(&s_M[s]);
        #pragma unroll
        for (int r = 0; r < 8; r++) { st_cl(aE, r, El); st_cl(aM, r, Ml); }
    }
    CSYNC();
    float Et = 0.f, Mt = 0.f;
    #pragma unroll
    for (int i = 0; i < 8; i++) { Et += s_E[i]; Mt += s_M[i]; }
    const float inv = 1.0f / (Mt + 1e-13f * Et);

    const int d0v = lane * 4, d1v = 128 + lane * 4;
    const bool v1 = (lane < 18);
    float4 a0 = {0,0,0,0}, a1 = {0,0,0,0};
    const float* hb = H + (size_t)n * 204800 + (size_t)s * 128 * 200;
    #pragma unroll 4
    for (int t = wid * 16; t < wid * 16 + 16; t++) {
        const float av = sa[t];
        const float* hr = hb + (size_t)t * 200;
        const float4 h0 = *(const float4*)(hr + d0v);
        a0.x += av * h0.x; a0.y += av * h0.y; a0.z += av * h0.z; a0.w += av * h0.w;
        if (v1) {
            const float4 h1 = *(const float4*)(hr + d1v);
            a1.x += av * h1.x; a1.y += av * h1.y; a1.z += av * h1.z; a1.w += av * h1.w;
        }
    }
    *(float4*)(&part[wid][d0v]) = a0;
    if (v1) *(float4*)(&part[wid][d1v]) = a1;
    __syncthreads();
    if (tid < 200) {
        float sum = 0.f;
        #pragma unroll
        for (int w = 0; w < 8; w++) sum += part[w][tid];
        ppart[tid] = sum;
    }
    CSYNC();
    if (tid < 200) {
        const unsigned a = smem_u32(&ppart[tid]);
        float sum = 0.f;
        #pragma unroll
        for (int r = 0; r < 8; r++) sum += ld_cl(a, r);
        hbar[tid] = sum * inv;
    }
    CSYNC();
    __syncthreads();

    float* gb = G + (size_t)(n * 1024 + s * 128) * 800;
    #pragma unroll 1
    for (int i = tid; i < 6400; i += 256) {
        const int r = i / 50, cc = i - r * 50;
        const float4 h4 = *(const float4*)(hb + (size_t)r * 200 + cc * 4);
        const float4 b4 = *(const float4*)(hbar + cc * 4);
        float4 o = {h4.x * b4.x, h4.y * b4.y, h4.z * b4.z, h4.w * b4.w};
        *(float4*)(gb + (size_t)r * 800 + 600 + cc * 4) = o;
    }
}

extern "C" void kernel_launch(void* const* d_in, const int* in_sizes, int n_in,
                              void* d_out, int out_size)
{
    const float* H      = (const float*)d_in[0];
    const float* U      = (const float*)d_in[1];
    const float* c_mask = (const float*)d_in[2];
    const float* q_mask = (const float*)d_in[3];
    const float* w      = (const float*)d_in[4];
    const float* b      = (const float*)d_in[5];
    float* G = (float*)d_out;

    cudaFuncSetAttribute(bi_attn_main, cudaFuncAttributeMaxDynamicSharedMemorySize, SMEM_BYTES);
    bi_attn_main<<<GRID_MAIN, 256, SMEM_BYTES>>>(H, U, q_mask, w, b, G);
    tail_fused<<<512, 256>>>(H, c_mask, G);
}

// round 17
// speedup vs baseline: 1.3548x; 1.3548x over previous
#include <cuda_runtime.h>
#include <cuda_fp16.h>
#include <cstdint>

// BiAttention (BiDAF): N=64, T=1024, J=64, D2=200.
// Main: fp16 mma.sync + ldmatrix(+trans), two-phase A staging, 55.6KB smem -> 3 CTAs/SM.
#define NEGV (-10000000.0f)
__device__ float g_Smax[64 * 1024];

// words: sA [128 x 52] @0 ; sB [64 x 100] @6656 ; sW @13056 ; hwh ; uwu ; qm
#define WB_B  6656
#define OFF_W   52224
#define OFF_HWH 54624
#define OFF_UWU 55136
#define OFF_QM  55392
#define SMEM_BYTES 55648

__device__ __forceinline__ void mma16816(float* c, uint32_t a0, uint32_t a1, uint32_t a2, uint32_t a3,
                                         uint32_t b0, uint32_t b1) {
    asm volatile("mma.sync.aligned.m16n8k16.row.col.f32.f16.f16.f32 "
                 "{%0,%1,%2,%3},{%4,%5,%6,%7},{%8,%9},{%0,%1,%2,%3};"
                 : "+f"(c[0]), "+f"(c[1]), "+f"(c[2]), "+f"(c[3])
                 : "r"(a0), "r"(a1), "r"(a2), "r"(a3), "r"(b0), "r"(b1));
}
__device__ __forceinline__ void mma1688(float* c, uint32_t a0, uint32_t a1, uint32_t b0) {
    asm volatile("mma.sync.aligned.m16n8k8.row.col.f32.f16.f16.f32 "
                 "{%0,%1,%2,%3},{%4,%5},{%6},{%0,%1,%2,%3};"
                 : "+f"(c[0]), "+f"(c[1]), "+f"(c[2]), "+f"(c[3])
                 : "r"(a0), "r"(a1), "r"(b0));
}
__device__ __forceinline__ void ldsm4(uint32_t* r, unsigned a) {
    asm volatile("ldmatrix.sync.aligned.m8n8.x4.shared.b16 {%0,%1,%2,%3}, [%4];"
                 : "=r"(r[0]), "=r"(r[1]), "=r"(r[2]), "=r"(r[3]) : "r"(a));
}
__device__ __forceinline__ void ldsm4t(uint32_t* r, unsigned a) {
    asm volatile("ldmatrix.sync.aligned.m8n8.x4.trans.shared.b16 {%0,%1,%2,%3}, [%4];"
                 : "=r"(r[0]), "=r"(r[1]), "=r"(r[2]), "=r"(r[3]) : "r"(a));
}
__device__ __forceinline__ void ldsm2t(uint32_t* r, unsigned a) {
    asm volatile("ldmatrix.sync.aligned.m8n8.x2.trans.shared.b16 {%0,%1}, [%2];"
                 : "=r"(r[0]), "=r"(r[1]) : "r"(a));
}
__device__ __forceinline__ uint32_t pack2h(float a, float b) {
    __half2 h = __floats2half2_rn(a, b);
    return *(uint32_t*)&h;
}
__device__ __forceinline__ unsigned smem_u32(const void* p) {
    unsigned a;
    asm("{ .reg .u64 t; cvta.to.shared.u64 t, %1; cvt.u32.u64 %0, t; }" : "=r"(a) : "l"(p));
    return a;
}

__global__ void __launch_bounds__(256, 3)
bi_attn_main(const float* __restrict__ H, const float* __restrict__ U,
             const float* __restrict__ q_mask, const float* __restrict__ wv,
             const float* __restrict__ bptr, float* __restrict__ G)
{
    extern __shared__ char smc[];
    uint32_t* sm32 = (uint32_t*)smc;
    const unsigned sb = smem_u32(smc);
    float* sW   = (float*)(smc + OFF_W);
    float* sHwh = (float*)(smc + OFF_HWH);
    float* sUwu = (float*)(smc + OFF_UWU);
    float* sQm  = (float*)(smc + OFF_QM);

    const int tid = threadIdx.x, wid = tid >> 5, lane = tid & 31;
    const int n = blockIdx.y, m0 = blockIdx.x * 128;
    const float bval = bptr[0];

    for (int i = tid; i < 600; i += 256) sW[i] = wv[i];
    if (tid < 64) sQm[tid] = q_mask[n * 64 + tid];
    __syncthreads();   // *** sW/sQm visible before staging (R16's missing barrier) ***

    const int ar = tid >> 1, ah = tid & 1;
    const int bj = tid >> 2, bq = tid & 3;
    const int r = lane >> 2, cq = lane & 3;
    const int li = lane & 7, g = lane >> 3;

    // ldmatrix addresses
    const unsigned aLd = sb + (unsigned)(((wid * 16 + li + (g & 1) * 8) * 52 + (g >> 1) * 4) * 4);
    const unsigned bLd = sb + (unsigned)(((WB_B + (li + (g >> 1) * 8) * 100) + (g & 1) * 4) * 4);
    // trans loads for GEMM2 B (Ut from K-major sB)
    const unsigned uLdT = sb + (unsigned)(((WB_B + ((g & 1) * 8 + li) * 100) + (g >> 1) * 4) * 4);
    const unsigned uLdT2 = sb + (unsigned)(((WB_B + (((lane >> 3) & 1) * 8 + li) * 100)) * 4);

    const float* hrow = H + (size_t)(n * 1024 + m0 + ar) * 200;

    // ============ stage phase-1 A (k 0..95) + B full + uwu ============
    float hwh_acc = 0.f, uwu_acc = 0.f;
    {
        const float* hp = hrow + ah * 48;
        const float* whp = sW + ah * 48;
        const float* wup = sW + 400 + ah * 48;
        uint32_t* dst = sm32 + ar * 52 + ah * 24;
        #pragma unroll
        for (int c = 0; c < 12; c++) {
            const float4 h4 = *(const float4*)(hp + c * 4);
            const float4 wh = *(const float4*)(whp + c * 4);
            const float4 wu = *(const float4*)(wup + c * 4);
            hwh_acc += h4.x * wh.x + h4.y * wh.y + h4.z * wh.z + h4.w * wh.w;
            uint2 st;
            st.x = pack2h(h4.x * wu.x, h4.y * wu.y);
            st.y = pack2h(h4.z * wu.z, h4.w * wu.w);
            *(uint2*)(dst + c * 2) = st;
        }
    }
    {
        const float* urow = U + (size_t)(n * 64 + bj) * 200;
        uint32_t* dst = sm32 + WB_B + bj * 100;
        #pragma unroll
        for (int c = bq; c < 50; c += 4) {
            const float4 u4 = *(const float4*)(urow + c * 4);
            const float4 wu = *(const float4*)(sW + 200 + c * 4);
            uwu_acc += u4.x * wu.x + u4.y * wu.y + u4.z * wu.z + u4.w * wu.w;
            uint2 st;
            st.x = pack2h(u4.x, u4.y);
            st.y = pack2h(u4.z, u4.w);
            *(uint2*)(dst + c * 2) = st;
        }
    }
    {
        float uv = uwu_acc;
        uv += __shfl_xor_sync(0xffffffffu, uv, 1);
        uv += __shfl_xor_sync(0xffffffffu, uv, 2);
        if (bq == 0) sUwu[bj] = uv;
    }
    __syncthreads();

    // ============ GEMM1 phase 1 (ksteps 0..5) ============
    float acc1[8][4];
    #pragma unroll
    for (int t = 0; t < 8; t++)
        #pragma unroll
        for (int u = 0; u < 4; u++) acc1[t][u] = 0.f;

    #pragma unroll 2
    for (int kst = 0; kst < 6; kst++) {
        uint32_t A[4];
        ldsm4(A, aLd + kst * 32);
        #pragma unroll
        for (int p = 0; p < 4; p++) {
            uint32_t Bv[4];
            ldsm4(Bv, bLd + p * 6400 + kst * 32);
            mma16816(acc1[2 * p],     A[0], A[1], A[2], A[3], Bv[0], Bv[1]);
            mma16816(acc1[2 * p + 1], A[0], A[1], A[2], A[3], Bv[2], Bv[3]);
        }
    }
    __syncthreads();   // phase-1 A reads done (WAR before restage)

    // ============ stage phase-2 A (k 96..199) ============
    {
        const float* hp = hrow + 96 + ah * 52;
        const float* whp = sW + 96 + ah * 52;
        const float* wup = sW + 496 + ah * 52;
        uint32_t* dst = sm32 + ar * 52 + ah * 26;
        #pragma unroll
        for (int c = 0; c < 13; c++) {
            const float4 h4 = *(const float4*)(hp + c * 4);
            const float4 wh = *(const float4*)(whp + c * 4);
            const float4 wu = *(const float4*)(wup + c * 4);
            hwh_acc += h4.x * wh.x + h4.y * wh.y + h4.z * wh.z + h4.w * wh.w;
            uint2 st;
            st.x = pack2h(h4.x * wu.x, h4.y * wu.y);
            st.y = pack2h(h4.z * wu.z, h4.w * wu.w);
            *(uint2*)(dst + c * 2) = st;
        }
        float hv = hwh_acc + __shfl_xor_sync(0xffffffffu, hwh_acc, 1);
        if (ah == 0) sHwh[ar] = hv;
    }
    __syncthreads();

    // ============ GEMM1 phase 2 (ksteps 6..11 + k8 tail) ============
    #pragma unroll 2
    for (int kst = 0; kst < 6; kst++) {
        uint32_t A[4];
        ldsm4(A, aLd + kst * 32);
        const int kb = (6 + kst) * 32;
        #pragma unroll
        for (int p = 0; p < 4; p++) {
            uint32_t Bv[4];
            ldsm4(Bv, bLd + p * 6400 + kb);
            mma16816(acc1[2 * p],     A[0], A[1], A[2], A[3], Bv[0], Bv[1]);
            mma16816(acc1[2 * p + 1], A[0], A[1], A[2], A[3], Bv[2], Bv[3]);
        }
    }
    {
        uint32_t A[4];
        ldsm4(A, aLd + 6 * 32);
        #pragma unroll
        for (int p = 0; p < 4; p++) {
            uint32_t Bv[4];
            ldsm4(Bv, bLd + p * 6400 + 12 * 32);
            mma1688(acc1[2 * p],     A[0], A[1], Bv[0]);
            mma1688(acc1[2 * p + 1], A[0], A[1], Bv[2]);
        }
    }

    // ============ softmax over j ============
    const int row0 = wid * 16 + r, row1 = row0 + 8;
    const float hwh0 = sHwh[row0], hwh1 = sHwh[row1];
    float mx0 = -3.4e38f, mx1 = -3.4e38f, smx0 = -3.4e38f, smx1 = -3.4e38f;
    #pragma unroll
    for (int nt = 0; nt < 8; nt++) {
        #pragma unroll
        for (int i = 0; i < 2; i++) {
            const int nn = nt * 8 + cq * 2 + i;
            const float q = sQm[nn], uw = sUwu[nn];
            const float s0 = acc1[nt][i] + hwh0 + uw + bval;
            const float s1 = acc1[nt][2 + i] + hwh1 + uw + bval;
            acc1[nt][i] = s0 * q; acc1[nt][2 + i] = s1 * q;
            mx0 = fmaxf(mx0, s0 * q); mx1 = fmaxf(mx1, s1 * q);
            smx0 = fmaxf(smx0, (q != 0.f) ? s0 : NEGV);
            smx1 = fmaxf(smx1, (q != 0.f) ? s1 : NEGV);
        }
    }
    #pragma unroll
    for (int o = 1; o <= 2; o <<= 1) {
        mx0 = fmaxf(mx0, __shfl_xor_sync(0xffffffffu, mx0, o));
        mx1 = fmaxf(mx1, __shfl_xor_sync(0xffffffffu, mx1, o));
        smx0 = fmaxf(smx0, __shfl_xor_sync(0xffffffffu, smx0, o));
        smx1 = fmaxf(smx1, __shfl_xor_sync(0xffffffffu, smx1, o));
    }
    float E0 = 0.f, M0 = 0.f, E1 = 0.f, M1 = 0.f;
    #pragma unroll
    for (int nt = 0; nt < 8; nt++) {
        #pragma unroll
        for (int i = 0; i < 2; i++) {
            const int nn = nt * 8 + cq * 2 + i;
            const float q = sQm[nn];
            const float e0 = __expf(acc1[nt][i] - mx0);
            const float e1 = __expf(acc1[nt][2 + i] - mx1);
            E0 += e0; E1 += e1;
            const float q0 = e0 * q, q1 = e1 * q;
            M0 += q0; M1 += q1;
            acc1[nt][i] = q0; acc1[nt][2 + i] = q1;
        }
    }
    #pragma unroll
    for (int o = 1; o <= 2; o <<= 1) {
        E0 += __shfl_xor_sync(0xffffffffu, E0, o);
        M0 += __shfl_xor_sync(0xffffffffu, M0, o);
        E1 += __shfl_xor_sync(0xffffffffu, E1, o);
        M1 += __shfl_xor_sync(0xffffffffu, M1, o);
    }
    const float inv0 = 1.0f / (M0 + 1e-13f * E0);
    const float inv1 = 1.0f / (M1 + 1e-13f * E1);
    if (cq == 0) {
        g_Smax[(n << 10) + m0 + row0] = smx0;
        g_Smax[(n << 10) + m0 + row1] = smx1;
    }

    // P (fp16) into this warp's OWN A rows (words 0..31) — warp-private
    #pragma unroll
    for (int nt = 0; nt < 8; nt++) {
        sm32[row0 * 52 + nt * 4 + cq] = pack2h(acc1[nt][0] * inv0, acc1[nt][1] * inv0);
        sm32[row1 * 52 + nt * 4 + cq] = pack2h(acc1[nt][2] * inv1, acc1[nt][3] * inv1);
    }
    __syncwarp();

    // ============ GEMM2: U_ = P @ U via ldmatrix.trans on sB ============
    const size_t grow0 = (size_t)(n * 1024 + m0 + row0) * 800;
    const size_t grow1 = (size_t)(n * 1024 + m0 + row1) * 800;
    const float* hg0 = H + (size_t)(n * 1024 + m0 + row0) * 200;
    const float* hg1 = H + (size_t)(n * 1024 + m0 + row1) * 200;

    #pragma unroll 1
    for (int pass = 0; pass < 5; pass++) {
        const int dbase = pass * 40;
        float acc2[5][4];
        #pragma unroll
        for (int t = 0; t < 5; t++)
            #pragma unroll
            for (int u = 0; u < 4; u++) acc2[t][u] = 0.f;

        #pragma unroll
        for (int kst = 0; kst < 4; kst++) {
            uint32_t A[4];
            ldsm4(A, aLd + kst * 32);
            const unsigned jofs = (unsigned)(kst * 6400);   // 16 j-rows * 400B
            #pragma unroll
            for (int q = 0; q < 2; q++) {
                uint32_t Bv[4];
                ldsm4t(Bv, uLdT + jofs + (unsigned)((dbase + q * 16) * 2));
                mma16816(acc2[2 * q],     A[0], A[1], A[2], A[3], Bv[0], Bv[1]);
                mma16816(acc2[2 * q + 1], A[0], A[1], A[2], A[3], Bv[2], Bv[3]);
            }
            uint32_t C2[2];
            ldsm2t(C2, uLdT2 + jofs + (unsigned)((dbase + 32) * 2));
            mma16816(acc2[4], A[0], A[1], A[2], A[3], C2[0], C2[1]);
        }
        #pragma unroll
        for (int nt = 0; nt < 5; nt++) {
            const int d = dbase + nt * 8 + cq * 2;
            const float2 h0 = *(const float2*)(hg0 + d);
            const float2 h1 = *(const float2*)(hg1 + d);
            float2 u0 = {acc2[nt][0], acc2[nt][1]};
            float2 u1 = {acc2[nt][2], acc2[nt][3]};
            float2 m0v = {h0.x * u0.x, h0.y * u0.y};
            float2 m1v = {h1.x * u1.x, h1.y * u1.y};
            *(float2*)(G + grow0 + d)       = h0;
            *(float2*)(G + grow0 + 200 + d) = u0;
            *(float2*)(G + grow0 + 400 + d) = m0v;
            *(float2*)(G + grow1 + d)       = h1;
            *(float2*)(G + grow1 + 200 + d) = u1;
            *(float2*)(G + grow1 + 400 + d) = m1v;
        }
    }
}

// ---- fused tail (unchanged, passing): cluster of 8 CTAs per n ----
__device__ __forceinline__ void st_cl(unsigned la, int rk, float v) {
    asm volatile("{ .reg .b32 ra; mapa.shared::cluster.u32 ra, %0, %1; st.shared::cluster.f32 [ra], %2; }"
                 :: "r"(la), "r"(rk), "f"(v) : "memory");
}
__device__ __forceinline__ float ld_cl(unsigned la, int rk) {
    float v;
    asm volatile("{ .reg .b32 ra; mapa.shared::cluster.u32 ra, %1, %2; ld.shared::cluster.f32 %0, [ra]; }"
                 : "=f"(v) : "r"(la), "r"(rk) : "memory");
    return v;
}
#define CSYNC() do { asm volatile("barrier.cluster.arrive.aligned;" ::: "memory"); \
                     asm volatile("barrier.cluster.wait.aligned;" ::: "memory"); } while (0)

__global__ void __launch_bounds__(256, 1) __cluster_dims__(8, 1, 1)
tail_fused(const float* __restrict__ H, const float* __restrict__ c_mask,
           float* __restrict__ G)
{
    __shared__ float sa[128];
    __shared__ float s_mx[8], s_E[8], s_M[8];
    __shared__ float red[8], redE[8], redM[8];
    __shared__ float part[8][208];
    __shared__ float ppart[200];
    __shared__ float hbar[200];

    const int bx = blockIdx.x, n = bx >> 3, s = bx & 7;
    const int tid = threadIdx.x, wid = tid >> 5, lane = tid & 31;

    float v = -3.4e38f, c = 0.f;
    if (tid < 128) {
        c = c_mask[n * 1024 + s * 128 + tid];
        v = g_Smax[n * 1024 + s * 128 + tid] * c;
    }
    float mx = v;
    #pragma unroll
    for (int o = 16; o > 0; o >>= 1) mx = fmaxf(mx, __shfl_xor_sync(0xffffffffu, mx, o));
    if (lane == 0) red[wid] = mx;
    __syncthreads();
    mx = red[0];
    #pragma unroll
    for (int i = 1; i < 8; i++) mx = fmaxf(mx, red[i]);
    if (tid == 0) {
        const unsigned a = smem_u32(&s_mx[s]);
        #pragma unroll
        for (int r = 0; r < 8; r++) st_cl(a, r, mx);
    }
    CSYNC();
    float gmx = s_mx[0];
    #pragma unroll
    for (int i = 1; i < 8; i++) gmx = fmaxf(gmx, s_mx[i]);

    float e = 0.f;
    if (tid < 128) { e = __expf(v - gmx); sa[tid] = e * c; }
    float El = e, Ml = e * c;
    #pragma unroll
    for (int o = 16; o > 0; o >>= 1) {
        El += __shfl_xor_sync(0xffffffffu, El, o);
        Ml += __shfl_xor_sync(0xffffffffu, Ml, o);
    }
    if (lane == 0) { redE[wid] = El; redM[wid] = Ml; }
    __syncthreads();
    El = 0.f; Ml = 0.f;
    #pragma unroll
    for (int i = 0; i < 8; i++) { El += redE[i]; Ml += redM[i]; }
    if (tid == 0) {
        const unsigned aE = smem_u32(&s_E[s]);
        const unsigned aM = smem_u32(&s_M[s]);
        #pragma unroll
        for (int r = 0; r < 8; r++) { st_cl(aE, r, El); st_cl(aM, r, Ml); }
    }
    CSYNC();
    float Et = 0.f, Mt = 0.f;
    #pragma unroll
    for (int i = 0; i < 8; i++) { Et += s_E[i]; Mt += s_M[i]; }
    const float inv = 1.0f / (Mt + 1e-13f * Et);

    const int d0v = lane * 4, d1v = 128 + lane * 4;
    const bool v1 = (lane < 18);
    float4 a0 = {0,0,0,0}, a1 = {0,0,0,0};
    const float* hb = H + (size_t)n * 204800 + (size_t)s * 128 * 200;
    #pragma unroll 4
    for (int t = wid * 16; t < wid * 16 + 16; t++) {
        const float av = sa[t];
        const float* hr = hb + (size_t)t * 200;
        const float4 h0 = *(const float4*)(hr + d0v);
        a0.x += av * h0.x; a0.y += av * h0.y; a0.z += av * h0.z; a0.w += av * h0.w;
        if (v1) {
            const float4 h1 = *(const float4*)(hr + d1v);
            a1.x += av * h1.x; a1.y += av * h1.y; a1.z += av * h1.z; a1.w += av * h1.w;
        }
    }
    *(float4*)(&part[wid][d0v]) = a0;
    if (v1) *(float4*)(&part[wid][d1v]) = a1;
    __syncthreads();
    if (tid < 200) {
        float sum = 0.f;
        #pragma unroll
        for (int w = 0; w < 8; w++) sum += part[w][tid];
        ppart[tid] = sum;
    }
    CSYNC();
    if (tid < 200) {
        const unsigned a = smem_u32(&ppart[tid]);
        float sum = 0.f;
        #pragma unroll
        for (int r = 0; r < 8; r++) sum += ld_cl(a, r);
        hbar[tid] = sum * inv;
    }
    CSYNC();
    __syncthreads();

    float* gb = G + (size_t)(n * 1024 + s * 128) * 800;
    #pragma unroll 1
    for (int i = tid; i < 6400; i += 256) {
        const int r = i / 50, cc = i - r * 50;
        const float4 h4 = *(const float4*)(hb + (size_t)r * 200 + cc * 4);
        const float4 b4 = *(const float4*)(hbar + cc * 4);
        float4 o = {h4.x * b4.x, h4.y * b4.y, h4.z * b4.z, h4.w * b4.w};
        *(float4*)(gb + (size_t)r * 800 + 600 + cc * 4) = o;
    }
}

extern "C" void kernel_launch(void* const* d_in, const int* in_sizes, int n_in,
                              void* d_out, int out_size)
{
    const float* H      = (const float*)d_in[0];
    const float* U      = (const float*)d_in[1];
    const float* c_mask = (const float*)d_in[2];
    const float* q_mask = (const float*)d_in[3];
    const float* w      = (const float*)d_in[4];
    const float* b      = (const float*)d_in[5];
    float* G = (float*)d_out;

    cudaFuncSetAttribute(bi_attn_main, cudaFuncAttributeMaxDynamicSharedMemorySize, SMEM_BYTES);
    dim3 g1(8, 64);
    bi_attn_main<<<g1, 256, SMEM_BYTES>>>(H, U, q_mask, w, b, G);
    tail_fused<<<512, 256>>>(H, c_mask, G);
}